// round 2
// baseline (speedup 1.0000x reference)
#include <cuda_runtime.h>
#include <math.h>

#define N_NODES 100000
#define E_EDGES 1600000
#define E2      (E_EDGES + N_NODES)   // 1,700,000 (edges + self loops)
#define IN_C    128
#define HID     64
#define HEADS   4
#define HH      (HEADS * HID)         // 256
#define OUT_C   2
#define NEG_SLOPE 0.2f

// ---------------- scratch (static device globals; no runtime allocs) -------
__device__ __align__(16) int   g_src[E2];
__device__ __align__(16) int   g_dst[E2];
__device__ __align__(16) float g_deg[N_NODES];
__device__ __align__(16) float g_dinv[N_NODES];
__device__ __align__(16) float g_norm[E2];
__device__ __align__(16) float g_xw1[(size_t)N_NODES * HID];
__device__ __align__(16) float g_h0 [(size_t)N_NODES * HID];
__device__ __align__(16) float g_xw2[(size_t)N_NODES * HH];
__device__ __align__(16) float g_h2 [(size_t)N_NODES * HH];
__device__ __align__(16) float g_as [(size_t)N_NODES * HEADS];
__device__ __align__(16) float g_ad [(size_t)N_NODES * HEADS];
__device__ __align__(16) float g_m  [(size_t)N_NODES * HEADS];
__device__ __align__(16) float g_den[(size_t)N_NODES * HEADS];
__device__ __align__(16) float g_alpha[(size_t)E2 * HEADS];
__device__ __align__(16) float g_hw3[(size_t)N_NODES * OUT_C];

// ---------------- helpers ---------------------------------------------------
__device__ __forceinline__ void redAdd4(float* p, float a, float b, float c, float d) {
    asm volatile("red.global.add.v4.f32 [%0], {%1,%2,%3,%4};"
                 :: "l"(p), "f"(a), "f"(b), "f"(c), "f"(d) : "memory");
}

__device__ __forceinline__ void atomicMaxFloat(float* addr, float value) {
    if (value >= 0.0f) atomicMax((int*)addr, __float_as_int(value));
    else               atomicMin((unsigned int*)addr, __float_as_uint(value));
}

__device__ __forceinline__ float lrelu(float x) { return x > 0.0f ? x : NEG_SLOPE * x; }

// ---------------- kernels ---------------------------------------------------
__global__ void k_zero(float* out) {
    int i = blockIdx.x * blockDim.x + threadIdx.x;
    if (i < N_NODES * HH)    g_h2[i] = 0.0f;
    if (i < N_NODES * HID)   g_h0[i] = 0.0f;
    if (i < N_NODES * HEADS) { g_m[i] = -3.402823466e38f; g_den[i] = 0.0f; }
    if (i < N_NODES)         g_deg[i] = 0.0f;
    if (i < N_NODES * OUT_C) out[i] = 0.0f;
}

// edge_index is int32 in the harness (JAX default x64-disabled demotes int64)
__global__ void k_edges(const int* __restrict__ ei) {
    int e = blockIdx.x * blockDim.x + threadIdx.x;
    if (e >= E2) return;
    int s, d;
    if (e < E_EDGES) { s = ei[e]; d = ei[E_EDGES + e]; }
    else             { s = e - E_EDGES; d = s; }
    g_src[e] = s; g_dst[e] = d;
    atomicAdd(&g_deg[d], 1.0f);
}

__global__ void k_dinv() {
    int i = blockIdx.x * blockDim.x + threadIdx.x;
    if (i < N_NODES) {
        float dg = g_deg[i];
        g_dinv[i] = dg > 0.0f ? rsqrtf(dg) : 0.0f;
    }
}

__global__ void k_norm() {
    int e = blockIdx.x * blockDim.x + threadIdx.x;
    if (e < E2) g_norm[e] = g_dinv[g_src[e]] * g_dinv[g_dst[e]];
}

// xw1 = x @ W1     x:[N,128]  W1:[128,64]
__global__ void k_gemm1(const float* __restrict__ x, const float* __restrict__ W1) {
    __shared__ __align__(16) float As[16][IN_C + 4];
    __shared__ __align__(16) float Bs[IN_C][HID];
    int tid = threadIdx.x;                       // 256 threads
    // load W1 (128x64 = 2048 float4)
    for (int i = tid; i < IN_C * HID / 4; i += 256)
        ((float4*)&Bs[0][0])[i] = ((const float4*)W1)[i];
    int row0 = blockIdx.x * 16;
    // load A tile (16 rows x 128)
    for (int i = tid; i < 16 * IN_C / 4; i += 256) {
        int r = i / (IN_C / 4), k4 = i % (IN_C / 4);
        *(float4*)&As[r][k4 * 4] =
            *(const float4*)&x[(size_t)(row0 + r) * IN_C + k4 * 4];
    }
    __syncthreads();
    int r = tid >> 4, cg = tid & 15;             // 4 cols per thread
    float a0 = 0, a1 = 0, a2 = 0, a3 = 0;
    #pragma unroll 8
    for (int k = 0; k < IN_C; k++) {
        float a = As[r][k];
        float4 b = *(const float4*)&Bs[k][cg * 4];
        a0 += a * b.x; a1 += a * b.y; a2 += a * b.z; a3 += a * b.w;
    }
    float4 o; o.x = a0; o.y = a1; o.z = a2; o.w = a3;
    *(float4*)&g_xw1[(size_t)(row0 + r) * HID + cg * 4] = o;
}

// GCN-1 scatter: h0[d] += xw1[s] * norm   (16 float4 chunks per edge)
__global__ void k_gcn1() {
    long long idx = (long long)blockIdx.x * blockDim.x + threadIdx.x;
    if (idx >= (long long)E2 * 16) return;
    int e  = (int)(idx >> 4);
    int c4 = (int)(idx & 15);
    int s = g_src[e], d = g_dst[e];
    float nrm = g_norm[e];
    float4 v = *(const float4*)&g_xw1[(size_t)s * HID + c4 * 4];
    redAdd4(&g_h0[(size_t)d * HID + c4 * 4], v.x * nrm, v.y * nrm, v.z * nrm, v.w * nrm);
}

__global__ void k_bias_relu(const float* __restrict__ b1) {
    int i = blockIdx.x * blockDim.x + threadIdx.x;
    if (i < N_NODES * HID)
        g_h0[i] = fmaxf(g_h0[i] + b1[i & (HID - 1)], 0.0f);
}

// xw2 = h0 @ W2  (fused attention dot products a_s, a_d)
__global__ void k_gemm2(const float* __restrict__ W2,
                        const float* __restrict__ attS,
                        const float* __restrict__ attD) {
    __shared__ __align__(16) float As[16][HID + 4];
    __shared__ __align__(16) float Bs[HID][128];
    __shared__ float aS[2][HID], aD[2][HID];
    int tid = threadIdx.x;                       // 256
    int row0 = blockIdx.x * 16;
    for (int i = tid; i < 16 * HID / 4; i += 256) {
        int r = i / (HID / 4), k4 = i % (HID / 4);
        *(float4*)&As[r][k4 * 4] =
            *(const float4*)&g_h0[(size_t)(row0 + r) * HID + k4 * 4];
    }
    int r = tid >> 4, cg = tid & 15;             // 8 cols per thread per half
    for (int half = 0; half < 2; half++) {
        __syncthreads();
        for (int i = tid; i < HID * 128 / 4; i += 256) {
            int k = i / 32, c4 = i % 32;
            *(float4*)&Bs[k][c4 * 4] =
                *(const float4*)&W2[(size_t)k * HH + half * 128 + c4 * 4];
        }
        if (tid < 128) {
            aS[tid >> 6][tid & 63] = attS[half * 128 + tid];
            aD[tid >> 6][tid & 63] = attD[half * 128 + tid];
        }
        __syncthreads();
        float acc[8];
        #pragma unroll
        for (int j = 0; j < 8; j++) acc[j] = 0.0f;
        #pragma unroll 8
        for (int k = 0; k < HID; k++) {
            float a = As[r][k];
            float4 b0 = *(const float4*)&Bs[k][cg * 8];
            float4 b1 = *(const float4*)&Bs[k][cg * 8 + 4];
            acc[0] += a * b0.x; acc[1] += a * b0.y; acc[2] += a * b0.z; acc[3] += a * b0.w;
            acc[4] += a * b1.x; acc[5] += a * b1.y; acc[6] += a * b1.z; acc[7] += a * b1.w;
        }
        int colbase = half * 128 + cg * 8;
        float4 o0; o0.x = acc[0]; o0.y = acc[1]; o0.z = acc[2]; o0.w = acc[3];
        float4 o1; o1.x = acc[4]; o1.y = acc[5]; o1.z = acc[6]; o1.w = acc[7];
        size_t base = (size_t)(row0 + r) * HH + colbase;
        *(float4*)&g_xw2[base]     = o0;
        *(float4*)&g_xw2[base + 4] = o1;
        // attention partials
        int hloc = cg >> 3;            // 0/1 within this half
        int off  = (cg & 7) * 8;
        float ps = 0.0f, pd = 0.0f;
        #pragma unroll
        for (int j = 0; j < 8; j++) {
            ps += acc[j] * aS[hloc][off + j];
            pd += acc[j] * aD[hloc][off + j];
        }
        // reduce across the 8 contiguous lanes of this (row, head) group
        #pragma unroll
        for (int o = 4; o >= 1; o >>= 1) {
            ps += __shfl_down_sync(0xffffffffu, ps, o);
            pd += __shfl_down_sync(0xffffffffu, pd, o);
        }
        if ((cg & 7) == 0) {
            int head = half * 2 + hloc;
            g_as[(size_t)(row0 + r) * HEADS + head] = ps;
            g_ad[(size_t)(row0 + r) * HEADS + head] = pd;
        }
    }
}

__global__ void k_gat_max() {
    int e = blockIdx.x * blockDim.x + threadIdx.x;
    if (e >= E2) return;
    int s = g_src[e], d = g_dst[e];
    float4 as4 = *(const float4*)&g_as[(size_t)s * HEADS];
    float4 ad4 = *(const float4*)&g_ad[(size_t)d * HEADS];
    atomicMaxFloat(&g_m[(size_t)d * HEADS + 0], lrelu(as4.x + ad4.x));
    atomicMaxFloat(&g_m[(size_t)d * HEADS + 1], lrelu(as4.y + ad4.y));
    atomicMaxFloat(&g_m[(size_t)d * HEADS + 2], lrelu(as4.z + ad4.z));
    atomicMaxFloat(&g_m[(size_t)d * HEADS + 3], lrelu(as4.w + ad4.w));
}

__global__ void k_gat_den() {
    int e = blockIdx.x * blockDim.x + threadIdx.x;
    if (e >= E2) return;
    int s = g_src[e], d = g_dst[e];
    float4 as4 = *(const float4*)&g_as[(size_t)s * HEADS];
    float4 ad4 = *(const float4*)&g_ad[(size_t)d * HEADS];
    float4 m4  = *(const float4*)&g_m [(size_t)d * HEADS];
    atomicAdd(&g_den[(size_t)d * HEADS + 0], expf(lrelu(as4.x + ad4.x) - m4.x));
    atomicAdd(&g_den[(size_t)d * HEADS + 1], expf(lrelu(as4.y + ad4.y) - m4.y));
    atomicAdd(&g_den[(size_t)d * HEADS + 2], expf(lrelu(as4.z + ad4.z) - m4.z));
    atomicAdd(&g_den[(size_t)d * HEADS + 3], expf(lrelu(as4.w + ad4.w) - m4.w));
}

__global__ void k_alpha() {
    int e = blockIdx.x * blockDim.x + threadIdx.x;
    if (e >= E2) return;
    int s = g_src[e], d = g_dst[e];
    float4 as4 = *(const float4*)&g_as [(size_t)s * HEADS];
    float4 ad4 = *(const float4*)&g_ad [(size_t)d * HEADS];
    float4 m4  = *(const float4*)&g_m  [(size_t)d * HEADS];
    float4 dn4 = *(const float4*)&g_den[(size_t)d * HEADS];
    float4 a;
    a.x = expf(lrelu(as4.x + ad4.x) - m4.x) / (dn4.x + 1e-16f);
    a.y = expf(lrelu(as4.y + ad4.y) - m4.y) / (dn4.y + 1e-16f);
    a.z = expf(lrelu(as4.z + ad4.z) - m4.z) / (dn4.z + 1e-16f);
    a.w = expf(lrelu(as4.w + ad4.w) - m4.w) / (dn4.w + 1e-16f);
    *(float4*)&g_alpha[(size_t)e * HEADS] = a;
}

// GAT aggregate: h2[d, h*64+c] += xw2[s, h*64+c] * alpha[e, h]
__global__ void k_gat_agg() {
    long long idx = (long long)blockIdx.x * blockDim.x + threadIdx.x;
    if (idx >= (long long)E2 * 64) return;
    int e = (int)(idx >> 6);
    int q = (int)(idx & 63);          // q = head*16 + chunk
    int head = q >> 4;
    int s = g_src[e], d = g_dst[e];
    float alpha = g_alpha[(size_t)e * HEADS + head];
    float4 v = *(const float4*)&g_xw2[(size_t)s * HH + q * 4];
    redAdd4(&g_h2[(size_t)d * HH + q * 4],
            v.x * alpha, v.y * alpha, v.z * alpha, v.w * alpha);
}

__global__ void k_bias_elu(const float* __restrict__ b2) {
    int i = blockIdx.x * blockDim.x + threadIdx.x;
    if (i < N_NODES * HH) {
        float v = g_h2[i] + b2[i & (HH - 1)];
        g_h2[i] = v > 0.0f ? v : expm1f(v);
    }
}

// hw3 = h2 @ W3   h2:[N,256]  W3:[256,2]   (warp per node)
__global__ void k_gemm3(const float* __restrict__ W3) {
    __shared__ float w0[HH], w1[HH];
    int tid = threadIdx.x;   // 256
    w0[tid] = W3[(size_t)tid * 2];
    w1[tid] = W3[(size_t)tid * 2 + 1];
    __syncthreads();
    int warp = tid >> 5, lane = tid & 31;
    int n = blockIdx.x * 8 + warp;
    if (n >= N_NODES) return;
    const float4* row = (const float4*)&g_h2[(size_t)n * HH];
    float4 v0 = row[lane], v1 = row[lane + 32];
    int c = lane * 4;
    float a0 = v0.x * w0[c] + v0.y * w0[c + 1] + v0.z * w0[c + 2] + v0.w * w0[c + 3]
             + v1.x * w0[c + 128] + v1.y * w0[c + 129] + v1.z * w0[c + 130] + v1.w * w0[c + 131];
    float a1 = v0.x * w1[c] + v0.y * w1[c + 1] + v0.z * w1[c + 2] + v0.w * w1[c + 3]
             + v1.x * w1[c + 128] + v1.y * w1[c + 129] + v1.z * w1[c + 130] + v1.w * w1[c + 131];
    #pragma unroll
    for (int o = 16; o >= 1; o >>= 1) {
        a0 += __shfl_xor_sync(0xffffffffu, a0, o);
        a1 += __shfl_xor_sync(0xffffffffu, a1, o);
    }
    if (lane == 0) {
        g_hw3[(size_t)n * 2]     = a0;
        g_hw3[(size_t)n * 2 + 1] = a1;
    }
}

__global__ void k_gcn2(float* __restrict__ out) {
    int e = blockIdx.x * blockDim.x + threadIdx.x;
    if (e >= E2) return;
    int s = g_src[e], d = g_dst[e];
    float nrm = g_norm[e];
    atomicAdd(&out[(size_t)d * 2],     g_hw3[(size_t)s * 2]     * nrm);
    atomicAdd(&out[(size_t)d * 2 + 1], g_hw3[(size_t)s * 2 + 1] * nrm);
}

__global__ void k_bias3(const float* __restrict__ b3, float* __restrict__ out) {
    int i = blockIdx.x * blockDim.x + threadIdx.x;
    if (i < N_NODES * OUT_C) out[i] += b3[i & 1];
}

// ---------------- launch -----------------------------------------------------
extern "C" void kernel_launch(void* const* d_in, const int* in_sizes, int n_in,
                              void* d_out, int out_size) {
    const float* x    = (const float*)d_in[0];
    const int*   ei   = (const int*)d_in[1];      // int32 (JAX x64-disabled)
    const float* W1   = (const float*)d_in[2];
    const float* b1   = (const float*)d_in[3];
    const float* W2   = (const float*)d_in[4];
    const float* attS = (const float*)d_in[5];
    const float* attD = (const float*)d_in[6];
    const float* b2   = (const float*)d_in[7];
    const float* W3   = (const float*)d_in[8];
    const float* b3   = (const float*)d_in[9];
    float* out = (float*)d_out;

    const int T = 256;
    k_zero     <<<(N_NODES * HH + T - 1) / T, T>>>(out);
    k_edges    <<<(E2 + T - 1) / T, T>>>(ei);
    k_dinv     <<<(N_NODES + T - 1) / T, T>>>();
    k_norm     <<<(E2 + T - 1) / T, T>>>();
    k_gemm1    <<<N_NODES / 16, T>>>(x, W1);
    k_gcn1     <<<(int)(((long long)E2 * 16 + T - 1) / T), T>>>();
    k_bias_relu<<<(N_NODES * HID + T - 1) / T, T>>>(b1);
    k_gemm2    <<<N_NODES / 16, T>>>(W2, attS, attD);
    k_gat_max  <<<(E2 + T - 1) / T, T>>>();
    k_gat_den  <<<(E2 + T - 1) / T, T>>>();
    k_alpha    <<<(E2 + T - 1) / T, T>>>();
    k_gat_agg  <<<(int)(((long long)E2 * 64 + T - 1) / T), T>>>();
    k_bias_elu <<<(N_NODES * HH + T - 1) / T, T>>>(b2);
    k_gemm3    <<<(N_NODES + 7) / 8, T>>>(W3);
    k_gcn2     <<<(E2 + T - 1) / T, T>>>(out);
    k_bias3    <<<(N_NODES * OUT_C + T - 1) / T, T>>>(b3, out);
}

// round 3
// speedup vs baseline: 1.5516x; 1.5516x over previous
#include <cuda_runtime.h>
#include <math.h>

#define N_NODES 100000
#define E_EDGES 1600000
#define E2      (E_EDGES + N_NODES)   // 1,700,000 (edges + self loops)
#define IN_C    128
#define HID     64
#define HEADS   4
#define HH      (HEADS * HID)         // 256
#define OUT_C   2
#define NEG_SLOPE 0.2f
#define SCAN_T  1024

// ---------------- scratch (static device globals) --------------------------
__device__ __align__(16) int   g_src[E2];
__device__ __align__(16) int   g_dst[E2];
__device__ __align__(16) int   g_degi[N_NODES];
__device__ __align__(16) int   g_cnt[N_NODES];
__device__ __align__(16) int   g_rowptr[N_NODES + 1];
__device__ __align__(16) float g_dinv[N_NODES];
__device__ __align__(16) int   g_csr_src[E2];
__device__ __align__(16) float g_csr_norm[E2];
__device__ __align__(16) float g_xw1[(size_t)N_NODES * HID];
__device__ __align__(16) float g_h0 [(size_t)N_NODES * HID];
__device__ __align__(16) float g_xw2[(size_t)N_NODES * HH];
__device__ __align__(16) float g_as [(size_t)N_NODES * HEADS];
__device__ __align__(16) float g_ad [(size_t)N_NODES * HEADS];
__device__ __align__(16) float g_alpha[(size_t)E2 * HEADS];
__device__ __align__(16) float g_hw3[(size_t)N_NODES * OUT_C];

__device__ __forceinline__ float lrelu(float x) { return x > 0.0f ? x : NEG_SLOPE * x; }

// ---------------- CSR build -------------------------------------------------
__global__ void k_init() {
    int i = blockIdx.x * blockDim.x + threadIdx.x;
    if (i < N_NODES) { g_degi[i] = 0; g_cnt[i] = 0; }
}

__global__ void k_edges(const int* __restrict__ ei) {
    int e = blockIdx.x * blockDim.x + threadIdx.x;
    if (e >= E2) return;
    int s, d;
    if (e < E_EDGES) { s = ei[e]; d = ei[E_EDGES + e]; }
    else             { s = e - E_EDGES; d = s; }
    g_src[e] = s; g_dst[e] = d;
    atomicAdd(&g_degi[d], 1);
}

// single-block exclusive scan of degrees -> rowptr; also dinv
__global__ void k_scan() {
    __shared__ int part[SCAN_T];
    const int CH = (N_NODES + SCAN_T - 1) / SCAN_T;   // 98
    int t = threadIdx.x;
    int base = t * CH;
    int hi = min(base + CH, N_NODES);
    int sum = 0;
    for (int i = base; i < hi; i++) sum += g_degi[i];
    part[t] = sum;
    __syncthreads();
    for (int off = 1; off < SCAN_T; off <<= 1) {
        int v = (t >= off) ? part[t - off] : 0;
        __syncthreads();
        part[t] += v;
        __syncthreads();
    }
    int run = (t == 0) ? 0 : part[t - 1];
    for (int i = base; i < hi; i++) {
        g_rowptr[i] = run;
        int dg = g_degi[i];
        g_dinv[i] = dg > 0 ? rsqrtf((float)dg) : 0.0f;
        run += dg;
    }
    if (t == SCAN_T - 1) g_rowptr[N_NODES] = run;
}

__global__ void k_fill() {
    int e = blockIdx.x * blockDim.x + threadIdx.x;
    if (e >= E2) return;
    int s = g_src[e], d = g_dst[e];
    int pos = g_rowptr[d] + atomicAdd(&g_cnt[d], 1);
    g_csr_src[pos]  = s;
    g_csr_norm[pos] = g_dinv[s] * g_dinv[d];
}

// ---------------- GEMM 1: xw1 = x @ W1  [N,128]x[128,64] -------------------
__global__ void k_gemm1(const float* __restrict__ x, const float* __restrict__ W1) {
    __shared__ __align__(16) float As[16][IN_C + 4];
    __shared__ __align__(16) float Bs[IN_C][HID];
    int tid = threadIdx.x;                       // 256 threads
    for (int i = tid; i < IN_C * HID / 4; i += 256)
        ((float4*)&Bs[0][0])[i] = ((const float4*)W1)[i];
    int row0 = blockIdx.x * 16;
    for (int i = tid; i < 16 * IN_C / 4; i += 256) {
        int r = i / (IN_C / 4), k4 = i % (IN_C / 4);
        *(float4*)&As[r][k4 * 4] =
            *(const float4*)&x[(size_t)(row0 + r) * IN_C + k4 * 4];
    }
    __syncthreads();
    int r = tid >> 4, cg = tid & 15;             // 4 cols per thread
    float a0 = 0, a1 = 0, a2 = 0, a3 = 0;
    #pragma unroll 8
    for (int k = 0; k < IN_C; k++) {
        float a = As[r][k];
        float4 b = *(const float4*)&Bs[k][cg * 4];
        a0 += a * b.x; a1 += a * b.y; a2 += a * b.z; a3 += a * b.w;
    }
    float4 o; o.x = a0; o.y = a1; o.z = a2; o.w = a3;
    *(float4*)&g_xw1[(size_t)(row0 + r) * HID + cg * 4] = o;
}

// ---------------- GCN-1 gather: h0[d] = relu(sum xw1[s]*norm + b1) ---------
__global__ void k_gcn1(const float* __restrict__ b1) {
    int warp = (blockIdx.x * blockDim.x + threadIdx.x) >> 5;
    int lane = threadIdx.x & 31;
    if (warp >= N_NODES) return;
    int r0 = g_rowptr[warp], r1 = g_rowptr[warp + 1];
    float acc0 = 0.0f, acc1 = 0.0f;
    for (int e = r0; e < r1; e++) {
        int   s   = g_csr_src[e];       // broadcast
        float nrm = g_csr_norm[e];      // broadcast
        float2 v = *(const float2*)&g_xw1[(size_t)s * HID + lane * 2];
        acc0 += v.x * nrm; acc1 += v.y * nrm;
    }
    float2 o;
    o.x = fmaxf(acc0 + __ldg(&b1[lane * 2]),     0.0f);
    o.y = fmaxf(acc1 + __ldg(&b1[lane * 2 + 1]), 0.0f);
    *(float2*)&g_h0[(size_t)warp * HID + lane * 2] = o;
}

// ---------------- GEMM 2: xw2 = h0 @ W2 (+ attention dots) -----------------
__global__ void k_gemm2(const float* __restrict__ W2,
                        const float* __restrict__ attS,
                        const float* __restrict__ attD) {
    __shared__ __align__(16) float As[16][HID + 4];
    __shared__ __align__(16) float Bs[HID][128];
    __shared__ float aS[2][HID], aD[2][HID];
    int tid = threadIdx.x;                       // 256
    int row0 = blockIdx.x * 16;
    for (int i = tid; i < 16 * HID / 4; i += 256) {
        int r = i / (HID / 4), k4 = i % (HID / 4);
        *(float4*)&As[r][k4 * 4] =
            *(const float4*)&g_h0[(size_t)(row0 + r) * HID + k4 * 4];
    }
    int r = tid >> 4, cg = tid & 15;             // 8 cols per thread per half
    for (int half = 0; half < 2; half++) {
        __syncthreads();
        for (int i = tid; i < HID * 128 / 4; i += 256) {
            int k = i / 32, c4 = i % 32;
            *(float4*)&Bs[k][c4 * 4] =
                *(const float4*)&W2[(size_t)k * HH + half * 128 + c4 * 4];
        }
        if (tid < 128) {
            aS[tid >> 6][tid & 63] = attS[half * 128 + tid];
            aD[tid >> 6][tid & 63] = attD[half * 128 + tid];
        }
        __syncthreads();
        float acc[8];
        #pragma unroll
        for (int j = 0; j < 8; j++) acc[j] = 0.0f;
        #pragma unroll 8
        for (int k = 0; k < HID; k++) {
            float a = As[r][k];
            float4 b0 = *(const float4*)&Bs[k][cg * 8];
            float4 b1 = *(const float4*)&Bs[k][cg * 8 + 4];
            acc[0] += a * b0.x; acc[1] += a * b0.y; acc[2] += a * b0.z; acc[3] += a * b0.w;
            acc[4] += a * b1.x; acc[5] += a * b1.y; acc[6] += a * b1.z; acc[7] += a * b1.w;
        }
        int colbase = half * 128 + cg * 8;
        float4 o0; o0.x = acc[0]; o0.y = acc[1]; o0.z = acc[2]; o0.w = acc[3];
        float4 o1; o1.x = acc[4]; o1.y = acc[5]; o1.z = acc[6]; o1.w = acc[7];
        size_t base = (size_t)(row0 + r) * HH + colbase;
        *(float4*)&g_xw2[base]     = o0;
        *(float4*)&g_xw2[base + 4] = o1;
        int hloc = cg >> 3;
        int off  = (cg & 7) * 8;
        float ps = 0.0f, pd = 0.0f;
        #pragma unroll
        for (int j = 0; j < 8; j++) {
            ps += acc[j] * aS[hloc][off + j];
            pd += acc[j] * aD[hloc][off + j];
        }
        #pragma unroll
        for (int o = 4; o >= 1; o >>= 1) {
            ps += __shfl_down_sync(0xffffffffu, ps, o);
            pd += __shfl_down_sync(0xffffffffu, pd, o);
        }
        if ((cg & 7) == 0) {
            int head = half * 2 + hloc;
            g_as[(size_t)(row0 + r) * HEADS + head] = ps;
            g_ad[(size_t)(row0 + r) * HEADS + head] = pd;
        }
    }
}

// ---------------- fused GAT: softmax + aggregate + bias + ELU + GEMM3 ------
// warp per destination node; output hw3[node] = elu(gat_out + b2) @ W3
__global__ void __launch_bounds__(256) k_gat(const float* __restrict__ b2,
                                             const float* __restrict__ W3) {
    __shared__ float sW3[HH * 2];
    __shared__ float sb2[HH];
    int tid = threadIdx.x;
    sW3[tid * 2]     = W3[tid * 2];
    sW3[tid * 2 + 1] = W3[tid * 2 + 1];
    sb2[tid]         = b2[tid];
    __syncthreads();

    int warp = blockIdx.x * 8 + (tid >> 5);
    int lane = tid & 31;
    if (warp >= N_NODES) return;
    int r0 = g_rowptr[warp], r1 = g_rowptr[warp + 1];

    float4 ad4 = *(const float4*)&g_ad[(size_t)warp * HEADS];

    // pass 1: e = lrelu(a_s[src] + a_d[dst]); store; track max per head
    float m0 = -3.4e38f, m1 = -3.4e38f, m2 = -3.4e38f, m3 = -3.4e38f;
    for (int e = r0 + lane; e < r1; e += 32) {
        int s = g_csr_src[e];
        float4 as4 = *(const float4*)&g_as[(size_t)s * HEADS];
        float4 el;
        el.x = lrelu(as4.x + ad4.x);
        el.y = lrelu(as4.y + ad4.y);
        el.z = lrelu(as4.z + ad4.z);
        el.w = lrelu(as4.w + ad4.w);
        *(float4*)&g_alpha[(size_t)e * HEADS] = el;
        m0 = fmaxf(m0, el.x); m1 = fmaxf(m1, el.y);
        m2 = fmaxf(m2, el.z); m3 = fmaxf(m3, el.w);
    }
    #pragma unroll
    for (int o = 16; o >= 1; o >>= 1) {
        m0 = fmaxf(m0, __shfl_xor_sync(0xffffffffu, m0, o));
        m1 = fmaxf(m1, __shfl_xor_sync(0xffffffffu, m1, o));
        m2 = fmaxf(m2, __shfl_xor_sync(0xffffffffu, m2, o));
        m3 = fmaxf(m3, __shfl_xor_sync(0xffffffffu, m3, o));
    }

    // pass 2: w = exp(e - m); store back; accumulate den per head
    float d0 = 0.0f, d1 = 0.0f, d2 = 0.0f, d3 = 0.0f;
    for (int e = r0 + lane; e < r1; e += 32) {
        float4 el = *(const float4*)&g_alpha[(size_t)e * HEADS];
        float4 w;
        w.x = __expf(el.x - m0); w.y = __expf(el.y - m1);
        w.z = __expf(el.z - m2); w.w = __expf(el.w - m3);
        *(float4*)&g_alpha[(size_t)e * HEADS] = w;
        d0 += w.x; d1 += w.y; d2 += w.z; d3 += w.w;
    }
    #pragma unroll
    for (int o = 16; o >= 1; o >>= 1) {
        d0 += __shfl_xor_sync(0xffffffffu, d0, o);
        d1 += __shfl_xor_sync(0xffffffffu, d1, o);
        d2 += __shfl_xor_sync(0xffffffffu, d2, o);
        d3 += __shfl_xor_sync(0xffffffffu, d3, o);
    }
    int head = lane >> 3;                           // 8 lanes per head
    float den = (head == 0) ? d0 : (head == 1) ? d1 : (head == 2) ? d2 : d3;
    float inv = 1.0f / (den + 1e-16f);

    // pass 3: aggregate xw2[src] * w  (whole warp per edge, coalesced 1KB)
    float acc[8];
    #pragma unroll
    for (int j = 0; j < 8; j++) acc[j] = 0.0f;
    int col = lane * 8;
    for (int e = r0; e < r1; e++) {
        int s = g_csr_src[e];                       // broadcast
        float w = g_alpha[(size_t)e * HEADS + head];
        const float4* p = (const float4*)&g_xw2[(size_t)s * HH + col];
        float4 v0 = p[0], v1 = p[1];
        acc[0] += v0.x * w; acc[1] += v0.y * w;
        acc[2] += v0.z * w; acc[3] += v0.w * w;
        acc[4] += v1.x * w; acc[5] += v1.y * w;
        acc[6] += v1.z * w; acc[7] += v1.w * w;
    }

    // epilogue: normalize, +b2, ELU, then dot with W3 columns (fused gemm3)
    float a0 = 0.0f, a1 = 0.0f;
    #pragma unroll
    for (int j = 0; j < 8; j++) {
        int c = col + j;
        float v = acc[j] * inv + sb2[c];
        v = v > 0.0f ? v : expm1f(v);
        a0 += v * sW3[c * 2];
        a1 += v * sW3[c * 2 + 1];
    }
    #pragma unroll
    for (int o = 16; o >= 1; o >>= 1) {
        a0 += __shfl_xor_sync(0xffffffffu, a0, o);
        a1 += __shfl_xor_sync(0xffffffffu, a1, o);
    }
    if (lane == 0) {
        g_hw3[(size_t)warp * 2]     = a0;
        g_hw3[(size_t)warp * 2 + 1] = a1;
    }
}

// ---------------- GCN-2 gather: out[d] = sum hw3[s]*norm + b3 --------------
__global__ void k_gcn2(const float* __restrict__ b3, float* __restrict__ out) {
    int warp = (blockIdx.x * blockDim.x + threadIdx.x) >> 5;
    int lane = threadIdx.x & 31;
    if (warp >= N_NODES) return;
    int r0 = g_rowptr[warp], r1 = g_rowptr[warp + 1];
    float acc0 = 0.0f, acc1 = 0.0f;
    for (int e = r0 + lane; e < r1; e += 32) {
        int   s   = g_csr_src[e];
        float nrm = g_csr_norm[e];
        float2 v = *(const float2*)&g_hw3[(size_t)s * 2];
        acc0 += v.x * nrm; acc1 += v.y * nrm;
    }
    #pragma unroll
    for (int o = 16; o >= 1; o >>= 1) {
        acc0 += __shfl_xor_sync(0xffffffffu, acc0, o);
        acc1 += __shfl_xor_sync(0xffffffffu, acc1, o);
    }
    if (lane == 0) {
        out[(size_t)warp * 2]     = acc0 + __ldg(&b3[0]);
        out[(size_t)warp * 2 + 1] = acc1 + __ldg(&b3[1]);
    }
}

// ---------------- launch -----------------------------------------------------
extern "C" void kernel_launch(void* const* d_in, const int* in_sizes, int n_in,
                              void* d_out, int out_size) {
    const float* x    = (const float*)d_in[0];
    const int*   ei   = (const int*)d_in[1];      // int32
    const float* W1   = (const float*)d_in[2];
    const float* b1   = (const float*)d_in[3];
    const float* W2   = (const float*)d_in[4];
    const float* attS = (const float*)d_in[5];
    const float* attD = (const float*)d_in[6];
    const float* b2   = (const float*)d_in[7];
    const float* W3   = (const float*)d_in[8];
    const float* b3   = (const float*)d_in[9];
    float* out = (float*)d_out;

    const int T = 256;
    k_init  <<<(N_NODES + T - 1) / T, T>>>();
    k_edges <<<(E2 + T - 1) / T, T>>>(ei);
    k_scan  <<<1, SCAN_T>>>();
    k_fill  <<<(E2 + T - 1) / T, T>>>();
    k_gemm1 <<<N_NODES / 16, T>>>(x, W1);
    k_gcn1  <<<(N_NODES * 32 + T - 1) / T, T>>>(b1);
    k_gemm2 <<<N_NODES / 16, T>>>(W2, attS, attD);
    k_gat   <<<(N_NODES + 7) / 8, T>>>(b2, W3);
    k_gcn2  <<<(N_NODES * 32 + T - 1) / T, T>>>(b3, out);
}